// round 2
// baseline (speedup 1.0000x reference)
#include <cuda_runtime.h>
#include <math.h>
#include <float.h>

// ---------------------------------------------------------------------------
// MatchLSTM: B=128, P=K=64, E=H=300, V=50000, C=3
//
// Pipeline:
//  1) pack weights: keep only i,g,o gate rows (f unused, c0=0) -> [900,300]
//  2) G = embed[tokens] @ Wpack^T (fused gather GEMM), lstm_act -> h_s, h_t
//  3) s_proj = h_s @ W_s^T ; t_proj = h_t @ W_t^T
//  4) ht_pre = h_t @ Wh'^T  (precomputable half of match-LSTM gates)
//     hsWa   = h_s @ Wa'^T  (lets scan form gates as alpha-weighted row sum)
//  5) scan: 1 persistent block per batch, 64 sequential steps, no grid sync.
// ---------------------------------------------------------------------------

// ---- scratch (device globals; no allocations allowed) ----
constexpr size_t SZ_GATES = 8192ull * 900;
constexpr size_t SZ_H     = 8192ull * 300;
constexpr size_t OFF_GATES = 0;
constexpr size_t OFF_HS    = OFF_GATES + SZ_GATES;
constexpr size_t OFF_HT    = OFF_HS + SZ_H;
constexpr size_t OFF_SPROJ = OFF_HT + SZ_H;
constexpr size_t OFF_TPROJ = OFF_SPROJ + SZ_H;
constexpr size_t OFF_HTPRE = OFF_TPROJ + SZ_H;
constexpr size_t OFF_HSWA  = OFF_HTPRE + SZ_GATES;
constexpr size_t OFF_WP    = OFF_HSWA + SZ_GATES;
constexpr size_t OFF_WH    = OFF_WP  + 900ull * 300;
constexpr size_t OFF_WA    = OFF_WH  + 900ull * 300;
constexpr size_t OFF_WHM   = OFF_WA  + 900ull * 300;
constexpr size_t OFF_WMT   = OFF_WHM + 900ull * 300;
constexpr size_t OFF_BP    = OFF_WMT + 300ull * 300;
constexpr size_t OFF_BH    = OFF_BP + 900;
constexpr size_t OFF_BM    = OFF_BH + 900;
constexpr size_t BUF_TOTAL = OFF_BM + 900;

__device__ __align__(16) float g_buf[BUF_TOTAL];

__device__ __forceinline__ float sigmoidf_(float x) { return 1.f / (1.f + expf(-x)); }

// ---- weight packing: rows {i: 0..299, g: 600..899, o: 900..1199} -> 900 rows
__global__ void pack_weights(const float* __restrict__ Wih, const float* __restrict__ bih,
                             const float* __restrict__ bhh, int in_dim, int col_off,
                             float* __restrict__ Wout, float* __restrict__ bout)
{
    int idx = blockIdx.x * blockDim.x + threadIdx.x;
    if (idx < 900 * 300) {
        int j = idx / 300, k2 = idx % 300;
        int src = (j < 300) ? j : j + 300;  // i -> i ; g(300..599)->600.. ; o(600..899)->900..
        Wout[idx] = Wih[(size_t)src * in_dim + col_off + k2];
    }
    if (idx < 900) {
        int src = (idx < 300) ? idx : idx + 300;
        bout[idx] = bih[src] + bhh[src];
    }
}

__global__ void transpose_wm(const float* __restrict__ Wm, float* __restrict__ WmT)
{
    int idx = blockIdx.x * blockDim.x + threadIdx.x;
    if (idx < 300 * 300) {
        int d = idx / 300, j = idx % 300;
        WmT[idx] = Wm[(size_t)j * 300 + d];   // WmT[d][j] = Wm[j][d]
    }
}

// ---- tiled SGEMM: C[M,N] = A[M,K] @ B[N,K]^T ; optional token-gather on A rows
__global__ __launch_bounds__(256)
void sgemm_tn(const float* __restrict__ A, const int* __restrict__ tok,
              const float* __restrict__ B, float* __restrict__ C,
              int M, int N, int K)
{
    constexpr int BM = 128, BN = 64, BK = 16, TM = 8, TN = 4;
    __shared__ float As[BK][BM];
    __shared__ float Bs[BK][BN];
    const int tid  = threadIdx.x;
    const int tcol = tid & 15;
    const int trow = tid >> 4;
    const int mbase = blockIdx.y * BM;
    const int nbase = blockIdx.x * BN;

    float acc[TM][TN];
#pragma unroll
    for (int i = 0; i < TM; i++)
#pragma unroll
        for (int j = 0; j < TN; j++) acc[i][j] = 0.f;

    const int lrow = tid >> 2;          // 0..63
    const int lkq  = (tid & 3) << 2;    // 0,4,8,12

    for (int k0 = 0; k0 < K; k0 += BK) {
        // A tile: 128 rows x 16 k, 2 float4 per thread (gather via tok if set)
#pragma unroll
        for (int h = 0; h < 2; ++h) {
            const int r  = lrow + h * 64;
            const int gm = mbase + r;
            const int src = tok ? tok[gm] : gm;
            float4 v = make_float4(0.f, 0.f, 0.f, 0.f);
            const int kk = k0 + lkq;
            if (kk < K) v = *reinterpret_cast<const float4*>(A + (size_t)src * K + kk);
            As[lkq + 0][r] = v.x; As[lkq + 1][r] = v.y;
            As[lkq + 2][r] = v.z; As[lkq + 3][r] = v.w;
        }
        // B tile: 64 rows x 16 k, 1 float4 per thread
        {
            const int n = nbase + lrow;
            float4 v = make_float4(0.f, 0.f, 0.f, 0.f);
            const int kk = k0 + lkq;
            if (n < N && kk < K) v = *reinterpret_cast<const float4*>(B + (size_t)n * K + kk);
            Bs[lkq + 0][lrow] = v.x; Bs[lkq + 1][lrow] = v.y;
            Bs[lkq + 2][lrow] = v.z; Bs[lkq + 3][lrow] = v.w;
        }
        __syncthreads();
#pragma unroll
        for (int kk = 0; kk < BK; ++kk) {
            float ra[TM], rb[TN];
#pragma unroll
            for (int i = 0; i < TM; i++) ra[i] = As[kk][trow * TM + i];
#pragma unroll
            for (int j = 0; j < TN; j++) rb[j] = Bs[kk][tcol * TN + j];
#pragma unroll
            for (int i = 0; i < TM; i++)
#pragma unroll
                for (int j = 0; j < TN; j++) acc[i][j] += ra[i] * rb[j];
        }
        __syncthreads();
    }
#pragma unroll
    for (int i = 0; i < TM; i++) {
        const int m = mbase + trow * TM + i;
#pragma unroll
        for (int j = 0; j < TN; j++) {
            const int n = nbase + tcol * TN + j;
            if (n < N) C[(size_t)m * N + n] = acc[i][j];
        }
    }
}

// ---- lstm0 activation: h = sigmoid(o) * tanh(sigmoid(i) * tanh(g))
__global__ void lstm_act(const float* __restrict__ G, const float* __restrict__ bias,
                         float* __restrict__ h)
{
    int idx = blockIdx.x * blockDim.x + threadIdx.x;
    if (idx >= 8192 * 300) return;
    int m = idx / 300, j = idx % 300;
    const float* g = G + (size_t)m * 900;
    float gi = g[j]       + bias[j];
    float gg = g[j + 300] + bias[j + 300];
    float go = g[j + 600] + bias[j + 600];
    float c  = sigmoidf_(gi) * tanhf(gg);
    h[idx]   = sigmoidf_(go) * tanhf(c);
}

// ---- persistent per-batch scan: 64 sequential match-LSTM steps
// SMEM floats: sp 19200 | we 300 | hm 300 | mp 300 | tk 300 | gates 900 |
//              alpha 64 | hfin 300 | partA 900 | red 8   => 22572 floats
constexpr int SCAN_SMEM_FLOATS = 19200 + 300 + 300 + 300 + 300 + 900 + 64 + 300 + 900 + 8;
constexpr int SCAN_SMEM_BYTES  = SCAN_SMEM_FLOATS * 4;

__global__ __launch_bounds__(256)
void scan_kernel(const float* __restrict__ sproj, const float* __restrict__ tproj,
                 const float* __restrict__ htpre, const float* __restrict__ hsWa,
                 const float* __restrict__ WmT,   const float* __restrict__ w_e,
                 const float* __restrict__ biasM, const int* __restrict__ plen_a,
                 const int* __restrict__ hlen_a,  const float* __restrict__ fcw,
                 const float* __restrict__ fcb,   float* __restrict__ out)
{
    extern __shared__ float sm[];
    float* sp    = sm;              // [64][300] cached s_proj for this batch
    float* we_s  = sp + 19200;      // 300
    float* hm    = we_s + 300;      // 300
    float* mp    = hm + 300;        // 300
    float* tk    = mp + 300;        // 300
    float* gates = tk + 300;        // 900
    float* alpha = gates + 900;     // 64
    float* hfin  = alpha + 64;      // 300
    float* partA = hfin + 300;      // 900 (3 x 75 float4 partials)
    float* red   = partA + 900;     // 8

    const int b    = blockIdx.x;
    const int tid  = threadIdx.x;
    const int warp = tid >> 5, lane = tid & 31;

    const float* spg = sproj + (size_t)b * (64 * 300);
    for (int i = tid; i < 64 * 300; i += 256) sp[i] = spg[i];
    for (int i = tid; i < 300; i += 256) { we_s[i] = w_e[i]; hm[i] = 0.f; }
    const int plen = plen_a[b];
    const int hlen = hlen_a[b];
    __syncthreads();

    const float* hwg = hsWa + (size_t)b * (64 * 900);

    for (int k = 0; k < 64; ++k) {
        // load t_k (consumed after two barriers below)
        const float* tkg = tproj + ((size_t)b * 64 + k) * 300;
        for (int i = tid; i < 300; i += 256) tk[i] = tkg[i];

        // Phase A: m_proj = hm @ Wm^T via pre-transposed WmT, float4 over j
        if (tid < 225) {
            const int jq  = tid % 75;
            const int seg = tid / 75;
            const int d0  = seg * 100;
            float4 acc = make_float4(0.f, 0.f, 0.f, 0.f);
#pragma unroll 4
            for (int d = d0; d < d0 + 100; ++d) {
                const float hv = hm[d];
                const float4 w = *reinterpret_cast<const float4*>(WmT + (size_t)d * 300 + jq * 4);
                acc.x += hv * w.x; acc.y += hv * w.y; acc.z += hv * w.z; acc.w += hv * w.w;
            }
            reinterpret_cast<float4*>(partA)[seg * 75 + jq] = acc;
        }
        __syncthreads();
        if (tid < 75) {
            float4 a0 = reinterpret_cast<float4*>(partA)[tid];
            float4 a1 = reinterpret_cast<float4*>(partA)[75 + tid];
            float4 a2 = reinterpret_cast<float4*>(partA)[150 + tid];
            reinterpret_cast<float4*>(mp)[tid] =
                make_float4(a0.x + a1.x + a2.x, a0.y + a1.y + a2.y,
                            a0.z + a1.z + a2.z, a0.w + a1.w + a2.w);
        }
        __syncthreads();

        // Phase B: e[p] = w_e . tanh(s_proj[p] + t_k + m_proj)
        for (int p = warp; p < 64; p += 8) {
            const float* sprow = sp + p * 300;
            float acc = 0.f;
            for (int h = lane; h < 300; h += 32) {
                float x = sprow[h] + tk[h] + mp[h];
                acc += we_s[h] * tanhf(x);
            }
#pragma unroll
            for (int o = 16; o > 0; o >>= 1) acc += __shfl_xor_sync(0xffffffffu, acc, o);
            if (lane == 0) alpha[p] = acc;
        }
        __syncthreads();

        // masked softmax over p (warp 0; plen >= 32 guaranteed but guard anyway)
        if (warp == 0) {
            float e0 = (lane < plen) ? alpha[lane] : -FLT_MAX;
            float e1 = (lane + 32 < plen) ? alpha[lane + 32] : -FLT_MAX;
            float mx = fmaxf(e0, e1);
#pragma unroll
            for (int o = 16; o > 0; o >>= 1) mx = fmaxf(mx, __shfl_xor_sync(0xffffffffu, mx, o));
            float x0 = (lane < plen) ? expf(e0 - mx) : 0.f;
            float x1 = (lane + 32 < plen) ? expf(e1 - mx) : 0.f;
            float s = x0 + x1;
#pragma unroll
            for (int o = 16; o > 0; o >>= 1) s += __shfl_xor_sync(0xffffffffu, s, o);
            float inv = 1.f / s;
            alpha[lane]      = x0 * inv;
            alpha[lane + 32] = x1 * inv;
        }
        __syncthreads();

        // Phase C: gates = sum_p alpha[p] * hsWa[b,p,:] + ht_pre[b,k,:] + biasM
        if (tid < 225) {
            float4 acc = make_float4(0.f, 0.f, 0.f, 0.f);
            for (int p = 0; p < 64; ++p) {
                const float ap = alpha[p];
                const float4 w = *reinterpret_cast<const float4*>(hwg + (size_t)p * 900 + tid * 4);
                acc.x += ap * w.x; acc.y += ap * w.y; acc.z += ap * w.z; acc.w += ap * w.w;
            }
            const float4 pre = *reinterpret_cast<const float4*>(htpre + ((size_t)b * 64 + k) * 900 + tid * 4);
            const float4 bs  = *reinterpret_cast<const float4*>(biasM + tid * 4);
            acc.x += pre.x + bs.x; acc.y += pre.y + bs.y;
            acc.z += pre.z + bs.z; acc.w += pre.w + bs.w;
            reinterpret_cast<float4*>(gates)[tid] = acc;
        }
        __syncthreads();

        // Phase D: h_m update (i,g,o packed layout)
        for (int h = tid; h < 300; h += 256) {
            float gi = gates[h];
            float gg = gates[h + 300];
            float go = gates[h + 600];
            float c  = sigmoidf_(gi) * tanhf(gg);
            float hv = sigmoidf_(go) * tanhf(c);
            hm[h] = hv;
            if (k == hlen - 1) hfin[h] = hv;
        }
        __syncthreads();
    }

    // logits = hfin @ fc_w^T + fc_b ; softmax over 3 classes
    if (warp < 3) {
        float acc = 0.f;
        for (int h = lane; h < 300; h += 32) acc += hfin[h] * fcw[warp * 300 + h];
#pragma unroll
        for (int o = 16; o > 0; o >>= 1) acc += __shfl_xor_sync(0xffffffffu, acc, o);
        if (lane == 0) red[warp] = acc + fcb[warp];
    }
    __syncthreads();
    if (tid == 0) {
        float l0 = red[0], l1 = red[1], l2 = red[2];
        float mx = fmaxf(l0, fmaxf(l1, l2));
        float e0 = expf(l0 - mx), e1 = expf(l1 - mx), e2 = expf(l2 - mx);
        float inv = 1.f / (e0 + e1 + e2);
        out[b * 3 + 0] = e0 * inv;
        out[b * 3 + 1] = e1 * inv;
        out[b * 3 + 2] = e2 * inv;
    }
}

// ---------------------------------------------------------------------------
extern "C" void kernel_launch(void* const* d_in, const int* in_sizes, int n_in,
                              void* d_out, int out_size)
{
    const int*   premise = (const int*)  d_in[0];
    const int*   plen    = (const int*)  d_in[1];
    const int*   hyp     = (const int*)  d_in[2];
    const int*   hlen    = (const int*)  d_in[3];
    const float* embed   = (const float*)d_in[4];
    const float* w_e     = (const float*)d_in[5];
    const float* W_s     = (const float*)d_in[6];
    const float* W_t     = (const float*)d_in[7];
    const float* W_m     = (const float*)d_in[8];
    const float* fc_w    = (const float*)d_in[9];
    const float* fc_b    = (const float*)d_in[10];
    const float* Wih_p   = (const float*)d_in[11];
    const float* bih_p   = (const float*)d_in[13];
    const float* bhh_p   = (const float*)d_in[14];
    const float* Wih_h   = (const float*)d_in[15];
    const float* bih_h   = (const float*)d_in[17];
    const float* bhh_h   = (const float*)d_in[18];
    const float* Wih_m   = (const float*)d_in[19];
    const float* bih_m   = (const float*)d_in[21];
    const float* bhh_m   = (const float*)d_in[22];

    float* buf = nullptr;
    cudaGetSymbolAddress((void**)&buf, g_buf);
    float* gates  = buf + OFF_GATES;
    float* hs     = buf + OFF_HS;
    float* ht     = buf + OFF_HT;
    float* sprojp = buf + OFF_SPROJ;
    float* tprojp = buf + OFF_TPROJ;
    float* htprep = buf + OFF_HTPRE;
    float* hsWap  = buf + OFF_HSWA;
    float* Wp     = buf + OFF_WP;
    float* Wh     = buf + OFF_WH;
    float* Wa     = buf + OFF_WA;
    float* Whm    = buf + OFF_WHM;
    float* WmT    = buf + OFF_WMT;
    float* bp     = buf + OFF_BP;
    float* bh     = buf + OFF_BH;
    float* bm     = buf + OFF_BM;

    // 1) pack weights (drop dead f-gate), transpose W_m
    pack_weights<<<(900 * 300 + 255) / 256, 256>>>(Wih_p, bih_p, bhh_p, 300, 0,   Wp,  bp);
    pack_weights<<<(900 * 300 + 255) / 256, 256>>>(Wih_h, bih_h, bhh_h, 300, 0,   Wh,  bh);
    pack_weights<<<(900 * 300 + 255) / 256, 256>>>(Wih_m, bih_m, bhh_m, 600, 0,   Wa,  bm);
    pack_weights<<<(900 * 300 + 255) / 256, 256>>>(Wih_m, bih_m, bhh_m, 600, 300, Whm, bm);
    transpose_wm<<<(300 * 300 + 255) / 256, 256>>>(W_m, WmT);

    dim3 blk(256);
    dim3 g900(15, 64);  // N=900 tiles x M=8192/128
    dim3 g300(5, 64);   // N=300 tiles

    // 2) encoders (fused embedding gather)
    sgemm_tn<<<g900, blk>>>(embed, premise, Wp, gates, 8192, 900, 300);
    lstm_act<<<9600, 256>>>(gates, bp, hs);
    sgemm_tn<<<g900, blk>>>(embed, hyp, Wh, gates, 8192, 900, 300);
    lstm_act<<<9600, 256>>>(gates, bh, ht);

    // 3) projections + scan-invariant precomputes
    sgemm_tn<<<g300, blk>>>(hs, nullptr, W_s, sprojp, 8192, 300, 300);
    sgemm_tn<<<g300, blk>>>(ht, nullptr, W_t, tprojp, 8192, 300, 300);
    sgemm_tn<<<g900, blk>>>(ht, nullptr, Whm, htprep, 8192, 900, 300);
    sgemm_tn<<<g900, blk>>>(hs, nullptr, Wa,  hsWap,  8192, 900, 300);

    // 4) sequential match-LSTM scan, one block per batch
    cudaFuncSetAttribute(scan_kernel, cudaFuncAttributeMaxDynamicSharedMemorySize,
                         SCAN_SMEM_BYTES);
    scan_kernel<<<128, 256, SCAN_SMEM_BYTES>>>(sprojp, tprojp, htprep, hsWap, WmT,
                                               w_e, bm, plen, hlen, fc_w, fc_b,
                                               (float*)d_out);
}